// round 17
// baseline (speedup 1.0000x reference)
#include <cuda_runtime.h>
#include <math.h>

// MPS log|Psi|^2, sm_103a — R16 numerics BIT-EXACT per column (pair fusion +
// e1 + Kahan, packed f32x2, sub-form), re-parallelized at 32 threads/sample:
// each thread owns ONE column-pair -> ~32 regs -> 2 CTAs/SM (1792 thr/SM,
// 14 warps/SMSP) to close the remaining latency exposure (R15 ncu: fma 65%,
// issue 60%, occ 44%). Only the final fp64 psi-reduction tree changes
// (2^-52-level). Prelude unchanged from R16.

#define NSITES  256
#define BATCH   8192
#define NGROUP  127
#define SPC     28                 // samples per CTA: 293*28 = 8204 >= 8192

__device__ float        g_Gh[(size_t)NGROUP * 4 * 4096];
__device__ unsigned int g_bits[BATCH * 8];

typedef unsigned long long ull;

__device__ __forceinline__ ull f2x_mul(ull a, ull b) {
    ull d; asm("mul.rn.f32x2 %0, %1, %2;" : "=l"(d) : "l"(a), "l"(b)); return d;
}
__device__ __forceinline__ ull f2x_add(ull a, ull b) {
    ull d; asm("add.rn.f32x2 %0, %1, %2;" : "=l"(d) : "l"(a), "l"(b)); return d;
}
__device__ __forceinline__ ull f2x_sub(ull a, ull b) {
    ull d; asm("sub.rn.f32x2 %0, %1, %2;" : "=l"(d) : "l"(a), "l"(b)); return d;
}
__device__ __forceinline__ ull f2x_fma(ull a, ull b, ull c) {
    ull d; asm("fma.rn.f32x2 %0, %1, %2, %3;" : "=l"(d) : "l"(a), "l"(b), "l"(c)); return d;
}
__device__ __forceinline__ ull packff(float x, float y) {
    ull d; asm("mov.b64 %0, {%1, %2};" : "=l"(d) : "f"(x), "f"(y)); return d;
}
__device__ __forceinline__ void unpackff(ull v, float& x, float& y) {
    asm("mov.b64 {%0, %1}, %2;" : "=f"(x), "=f"(y) : "l"(v));
}

// ------------------------------------------- ballot-based bit packing (~9us)
__global__ void pack_bits_kernel(const int* __restrict__ cfg) {
    int wid  = (blockIdx.x * blockDim.x + threadIdx.x) >> 5;   // word id
    int lane = threadIdx.x & 31;
    unsigned int v = (unsigned int)cfg[wid * 32 + lane];
    unsigned int word = __ballot_sync(0xFFFFFFFFu, v & 1u);
    if (lane == 0) g_bits[wid] = word;
}

// ------------- pair-product table, compensated, correctly-rounded fp32 output
// (arithmetic identical to R7/R11/R14/R16 — G bits define rel_err)
__global__ void build_G_kernel(const float* __restrict__ bulk) {
    __shared__ float As[64 * 65];
    __shared__ float Bs[64 * 68];
    int g = blockIdx.x, c = blockIdx.y;
    int v0 = c & 1, v1 = (c >> 1) & 1;
    int tid = threadIdx.x;
    const float* A = bulk + (size_t)(2 * g) * 8192 + v0 * 64;   // bulk[2g][i][v0][j]
    const float* B = bulk + (size_t)(2 * g + 1) * 8192 + v1 * 64;
    for (int n = tid; n < 4096; n += 256) {
        int i = n >> 6, j = n & 63;
        As[i * 65 + j] = A[i * 128 + j];
        Bs[i * 68 + j] = B[i * 128 + j];
    }
    __syncthreads();
    int r  = tid >> 2;
    int j0 = (tid & 3) * 16;
    float s[16], cc[16], ae[16];
#pragma unroll
    for (int q = 0; q < 16; q++) { s[q] = 0.f; cc[q] = 0.f; ae[q] = 0.f; }
#pragma unroll 8
    for (int k = 0; k < 64; k++) {
        float a = As[r * 65 + k];
#pragma unroll
        for (int q = 0; q < 16; q++) {
            float b  = Bs[k * 68 + j0 + q];
            float p  = a * b;
            float e1 = fmaf(a, b, -p);
            float y  = p - cc[q];
            float t  = s[q] + y;
            cc[q]    = (t - s[q]) - y;
            s[q]     = t;
            ae[q]   += e1;
        }
    }
    size_t base = ((size_t)(g * 4 + c) << 12) + r * 64 + j0;
#pragma unroll
    for (int q = 0; q < 16; q++)
        g_Gh[base + q] = s[q] + (ae[q] - cc[q]);    // ~correctly rounded
}

// --------------------------------------------------------------- main chain
__global__ __launch_bounds__(32 * SPC, 2)
void mps_main_kernel(const float* __restrict__ left,
                     const float* __restrict__ right,
                     float* __restrict__ out) {
    const int tid  = threadIdx.x;
    const int o    = tid & 31;                   // lane: owns cols [2o, 2o+2)
    const int row0 = blockIdx.x * SPC + (tid >> 5);
    const int row  = row0 < BATCH ? row0 : BATCH - 1;

    unsigned int B[8];
#pragma unroll
    for (int w = 0; w < 8; w++) B[w] = g_bits[row * 8 + w];
#define BIT(s) ((B[(s) >> 5] >> ((s) & 31)) & 1u)

    float env[2];
    {
        unsigned int b0 = BIT(0);
        env[0] = left[b0 * 64 + 2 * o + 0];
        env[1] = left[b0 * 64 + 2 * o + 1];
    }
    int ls2 = 0;

    for (int g = 0; g < NGROUP; g++) {
        unsigned int c = BIT(2 * g + 1) | (BIT(2 * g + 2) << 1);
        const float* __restrict__ Gm = g_Gh + ((size_t)(g * 4 + c) << 12) + 2 * o;

        ull s = 0ULL, nc = 0ULL, lo = 0ULL;

#pragma unroll
        for (int i = 0; i < 64; i++) {               // full unroll (same order)
            float eh  = __shfl_sync(0xFFFFFFFFu, env[i & 1], i >> 1, 32);
            float ehn = -eh;
            ull ep  = packff(eh,  eh);
            ull epn = packff(ehn, ehn);
            float2 h0 = *(const float2*)(Gm + (i << 6));
            ull h2 = packff(h0.x, h0.y);

            ull p   = f2x_mul(ep, h2);
            ull e1n = f2x_fma(epn, h2, p);           // = -(exact prod err)
            lo      = f2x_add(lo, e1n);              // lo = -sum(e1) exactly
            ull y   = f2x_add(p, nc);                // p - c
            ull t   = f2x_add(s, y);
            nc      = f2x_add(f2x_sub(s, t), y);     // -(new c)
            s       = t;
        }

        // fold: tot = s + (nc - lo)  ==  s + (nc + sum(e1))  bit-identical
        ull tot = f2x_add(s, f2x_sub(nc, lo));
        unpackff(tot, env[0], env[1]);
        float m = fmaxf(fabsf(env[0]), fabsf(env[1]));

        // exact power-of-2 rescale (32-lane max stays within the sample)
        m = fmaxf(m, __shfl_xor_sync(0xFFFFFFFFu, m, 1));
        m = fmaxf(m, __shfl_xor_sync(0xFFFFFFFFu, m, 2));
        m = fmaxf(m, __shfl_xor_sync(0xFFFFFFFFu, m, 4));
        m = fmaxf(m, __shfl_xor_sync(0xFFFFFFFFu, m, 8));
        m = fmaxf(m, __shfl_xor_sync(0xFFFFFFFFu, m, 16));
        int ef = (int)(__float_as_uint(m) >> 23);
        if (ef > 0) {
            ls2 += ef - 127;
            float sc = __uint_as_float((unsigned int)(254 - ef) << 23);
            env[0] *= sc;
            env[1] *= sc;
        }
    }

    // final contraction in fp64 (cancellation-sensitive, one-shot)
    unsigned int bl = BIT(255);
    double part = fma((double)env[0], (double)right[(2 * o + 0) * 2 + bl], 0.0);
    part = fma((double)env[1], (double)right[(2 * o + 1) * 2 + bl], part);
    part += __shfl_xor_sync(0xFFFFFFFFu, part, 1);
    part += __shfl_xor_sync(0xFFFFFFFFu, part, 2);
    part += __shfl_xor_sync(0xFFFFFFFFu, part, 4);
    part += __shfl_xor_sync(0xFFFFFFFFu, part, 8);
    part += __shfl_xor_sync(0xFFFFFFFFu, part, 16);

    if (o == 0 && row0 < BATCH) {
        double ap = fabs(part);
        if (ap < 1e-300) ap = 1e-300;
        out[row0] = (float)(2.0 * (log(ap) + (double)ls2 * 0.6931471805599453094));
    }
#undef BIT
}

// ------------------------------------------------------------------- launch
extern "C" void kernel_launch(void* const* d_in, const int* in_sizes, int n_in,
                              void* d_out, int out_size) {
    const int*   cfg   = (const int*)d_in[0];
    const float* left  = (const float*)d_in[1];
    const float* bulk  = (const float*)d_in[2];
    const float* right = (const float*)d_in[3];
    float*       out   = (float*)d_out;

    pack_bits_kernel<<<BATCH * 8 * 32 / 256, 256>>>(cfg);
    dim3 gg(NGROUP, 4);
    build_G_kernel<<<gg, 256>>>(bulk);
    mps_main_kernel<<<(BATCH + SPC - 1) / SPC, 32 * SPC>>>(left, right, out);
}